// round 16
// baseline (speedup 1.0000x reference)
#include <cuda_runtime.h>
#include <cuda_bf16.h>
#include <cuda_fp16.h>
#include <cstdint>
#include <math.h>

#define NQ   8192
#define NM   16384
#define DIM  1024
#define KNN  5
#define NCAND 16
#define MARGIN 24.0f

#define QSCALE 24.0f
#define INV_S2 (1.0f / (24.0f * 24.0f))

// ---------------- static device scratch (no allocations allowed) ----------------
__device__ __align__(256) int8_t   g_q8[(size_t)NQ * DIM];      // 8 MB
__device__ __align__(256) int8_t   g_m8[(size_t)NM * DIM];      // 16 MB
__device__ __align__(256) float    g_q2[NQ];
__device__ __align__(256) float    g_m2[NM];
__device__ __align__(256) __half   g_Sh[(size_t)NQ * NM];       // 256 MB scores d^2-q2 (fp16, >=0)
__device__ __align__(256) uint32_t g_cand[NQ * NCAND];          // ascending keys (fp16bits<<16|col)

// =============================== helpers ===============================
__device__ __forceinline__ uint32_t smem_u32(const void* p) {
    return (uint32_t)__cvta_generic_to_shared(p);
}
__device__ __forceinline__ void cpasync16(uint32_t s, const void* g) {
    asm volatile("cp.async.cg.shared.global [%0], [%1], 16;\n" :: "r"(s), "l"(g));
}
__device__ __forceinline__ void mma_s8(int* c, const uint32_t* a, uint32_t b0, uint32_t b1) {
    asm volatile(
        "mma.sync.aligned.m16n8k32.row.col.s32.s8.s8.s32 "
        "{%0,%1,%2,%3}, {%4,%5,%6,%7}, {%8,%9}, {%0,%1,%2,%3};\n"
        : "+r"(c[0]), "+r"(c[1]), "+r"(c[2]), "+r"(c[3])
        : "r"(a[0]), "r"(a[1]), "r"(a[2]), "r"(a[3]), "r"(b0), "r"(b1));
}
__device__ __forceinline__ void ldmx4(uint32_t* r, uint32_t addr) {
    asm volatile("ldmatrix.sync.aligned.m8n8.x4.shared.b16 {%0,%1,%2,%3}, [%4];\n"
                 : "=r"(r[0]), "=r"(r[1]), "=r"(r[2]), "=r"(r[3]) : "r"(addr));
}

// =============================== prep: quantize + row sumsq ===============================
__global__ void __launch_bounds__(256) prep_kernel(const float* __restrict__ src,
                                                   int8_t* __restrict__ dst,
                                                   float* __restrict__ sq, int nrows) {
    int warp = (blockIdx.x * blockDim.x + threadIdx.x) >> 5;
    int lane = threadIdx.x & 31;
    if (warp >= nrows) return;
    const float4* s4 = (const float4*)(src + (size_t)warp * DIM);
    uint32_t* d4 = (uint32_t*)(dst + (size_t)warp * DIM);
    float acc = 0.f;
#pragma unroll
    for (int c = 0; c < DIM / 128; ++c) {
        float4 v = s4[c * 32 + lane];
        acc += v.x * v.x + v.y * v.y + v.z * v.z + v.w * v.w;
        int qa = max(-127, min(127, __float2int_rn(v.x * QSCALE)));
        int qb = max(-127, min(127, __float2int_rn(v.y * QSCALE)));
        int qc = max(-127, min(127, __float2int_rn(v.z * QSCALE)));
        int qd = max(-127, min(127, __float2int_rn(v.w * QSCALE)));
        uint32_t p = (uint32_t)(uint8_t)(int8_t)qa |
                     ((uint32_t)(uint8_t)(int8_t)qb << 8) |
                     ((uint32_t)(uint8_t)(int8_t)qc << 16) |
                     ((uint32_t)(uint8_t)(int8_t)qd << 24);
        d4[c * 32 + lane] = p;
    }
#pragma unroll
    for (int o = 16; o; o >>= 1) acc += __shfl_xor_sync(0xffffffffu, acc, o);
    if (lane == 0) sq[warp] = acc;
}

// =============================== int8 GEMM (occ-2) + fp16 score epilogue ===============================
// CTA 128x128, warp tile 64x32 (warp grid 2x4), K stage = 64 bytes, 4 stages.
// 80 KB smem + <=128 regs -> 2 CTAs/SM (proven R15 config, GEMM ~472us ~= issue floor).
#define BM 128
#define BN 128
#define BKB 64
#define STAGES 4
#define AROW 80
#define A_ST (BM * AROW)                  // 10240
#define B_ST (BN * AROW)                  // 10240
#define STAGE_BYTES (A_ST + B_ST)         // 20480
#define SMEM_DYN (STAGES * STAGE_BYTES)   // 81920
#define KTILES (DIM / BKB)                // 16

__global__ void __launch_bounds__(256, 2) gemm_kernel() {
    extern __shared__ char smem[];
    const uint32_t sb = smem_u32(smem);

    const int tid  = threadIdx.x;
    const int wid  = tid >> 5;
    const int lane = tid & 31;
    const int wm = wid & 1;            // m offset wm*64
    const int wn = wid >> 1;           // n offset wn*32
    const size_t m0 = (size_t)blockIdx.y * BM;
    const size_t n0 = (size_t)blockIdx.x * BN;

    const char* Ag = (const char*)g_q8 + m0 * DIM;
    const char* Bg = (const char*)g_m8 + n0 * DIM;

    int acc[4][4][4];
#pragma unroll
    for (int i = 0; i < 4; ++i)
#pragma unroll
        for (int j = 0; j < 4; ++j)
#pragma unroll
            for (int c = 0; c < 4; ++c) acc[i][j][c] = 0;

    auto load_stage = [&](int t, int s) {
        const uint32_t st = sb + s * STAGE_BYTES;
#pragma unroll
        for (int i = 0; i < 2; ++i) {
            int c = tid + i * 256;
            int r = c >> 2, u = c & 3;
            cpasync16(st + r * AROW + u * 16, Ag + (size_t)r * DIM + t * BKB + u * 16);
        }
#pragma unroll
        for (int i = 0; i < 2; ++i) {
            int c = tid + i * 256;
            int r = c >> 2, u = c & 3;
            cpasync16(st + A_ST + r * AROW + u * 16, Bg + (size_t)r * DIM + t * BKB + u * 16);
        }
        asm volatile("cp.async.commit_group;\n");
    };

    load_stage(0, 0);
    load_stage(1, 1);
    load_stage(2, 2);

#pragma unroll 1
    for (int kt = 0; kt < KTILES; ++kt) {
        if (kt <= 13)      asm volatile("cp.async.wait_group 2;\n" ::: "memory");
        else if (kt == 14) asm volatile("cp.async.wait_group 1;\n" ::: "memory");
        else               asm volatile("cp.async.wait_group 0;\n" ::: "memory");
        __syncthreads();

        if (kt + 3 < KTILES) load_stage(kt + 3, (kt + 3) & 3);

        const uint32_t st = sb + (kt & 3) * STAGE_BYTES;
#pragma unroll
        for (int ks = 0; ks < 2; ++ks) {
            uint32_t a[4][4], b[2][4];
            const uint32_t aAddr = st + (wm * 64 + (lane & 15)) * AROW
                                 + ks * 32 + ((lane >> 4) << 4);
#pragma unroll
            for (int i = 0; i < 4; ++i) ldmx4(a[i], aAddr + i * 16 * AROW);
            const uint32_t bAddr = st + A_ST
                                 + (wn * 32 + (lane & 7) + ((lane & 16) ? 8 : 0)) * AROW
                                 + ks * 32 + ((lane & 8) ? 16 : 0);
#pragma unroll
            for (int j = 0; j < 2; ++j) ldmx4(b[j], bAddr + j * 16 * AROW);
#pragma unroll
            for (int i = 0; i < 4; ++i)
#pragma unroll
                for (int j = 0; j < 2; ++j) {
                    mma_s8(acc[i][2 * j + 0], a[i], b[j][0], b[j][1]);
                    mma_s8(acc[i][2 * j + 1], a[i], b[j][2], b[j][3]);
                }
        }
    }

    // ---- epilogue: v = m2[col] - 2*dot*INV_S2, clamp >= 0, store fp16 ----
    const int g = lane >> 2, tig = lane & 3;
    const float* m2base = g_m2 + n0 + wn * 32;
#pragma unroll
    for (int i = 0; i < 4; ++i) {
        size_t row = m0 + wm * 64 + i * 16 + g;
        __half* o0 = g_Sh + row * NM + n0 + wn * 32;
        __half* o1 = o0 + (size_t)8 * NM;
#pragma unroll
        for (int j = 0; j < 4; ++j) {
            int col = j * 8 + 2 * tig;
            float2 m2v = *(const float2*)(m2base + col);
            float v00 = fmaxf(m2v.x - 2.f * INV_S2 * __int2float_rn(acc[i][j][0]), 0.f);
            float v01 = fmaxf(m2v.y - 2.f * INV_S2 * __int2float_rn(acc[i][j][1]), 0.f);
            float v10 = fmaxf(m2v.x - 2.f * INV_S2 * __int2float_rn(acc[i][j][2]), 0.f);
            float v11 = fmaxf(m2v.y - 2.f * INV_S2 * __int2float_rn(acc[i][j][3]), 0.f);
            *(__half2*)(o0 + col) = __floats2half2_rn(v00, v01);
            *(__half2*)(o1 + col) = __floats2half2_rn(v10, v11);
        }
    }
}

// =============================== candidate selection (two rows per warp, ILP) ============
// Same per-row logic as the proven R3 scan; two independent rows interleaved per warp
// to break the loop-carried top[7] dependency chain. Outputs full keys, ascending.
__global__ void __launch_bounds__(256) select_kernel() {
    int warp = (blockIdx.x * blockDim.x + threadIdx.x) >> 5;
    int lane = threadIdx.x & 31;
    if (warp >= NQ / 2) return;
    const int r0 = warp * 2, r1 = r0 + 1;
    const __half* S0 = g_Sh + (size_t)r0 * NM;
    const __half* S1 = g_Sh + (size_t)r1 * NM;

    uint32_t tA[8], tB[8];
#pragma unroll
    for (int j = 0; j < 8; ++j) { tA[j] = 0xFFFFFFFFu; tB[j] = 0xFFFFFFFFu; }

    auto scan_word = [&](uint32_t w, uint32_t c0, uint32_t* top) {
        uint32_t klo = (w << 16) | c0;
        uint32_t khi = (w & 0xFFFF0000u) | (c0 + 1);
#pragma unroll
        for (int s = 0; s < 2; ++s) {
            uint32_t key = s ? khi : klo;
            if (key < top[7]) {
                top[7] = key;
#pragma unroll
                for (int j = 7; j > 0; --j)
                    if (top[j] < top[j - 1]) {
                        uint32_t t2 = top[j]; top[j] = top[j - 1]; top[j - 1] = t2;
                    }
            }
        }
    };

    for (int it = 0; it < NM / 256; ++it) {
        uint32_t c0 = (uint32_t)(it * 256 + lane * 8);
        uint4 a = *(const uint4*)(S0 + c0);
        uint4 b = *(const uint4*)(S1 + c0);
        scan_word(a.x, c0 + 0, tA);  scan_word(b.x, c0 + 0, tB);
        scan_word(a.y, c0 + 2, tA);  scan_word(b.y, c0 + 2, tB);
        scan_word(a.z, c0 + 4, tA);  scan_word(b.z, c0 + 4, tB);
        scan_word(a.w, c0 + 6, tA);  scan_word(b.w, c0 + 6, tB);
    }

    auto pops = [&](uint32_t* top, int r) {
        for (int t = 0; t < NCAND; ++t) {
            uint32_t mv = top[0];
#pragma unroll
            for (int j = 1; j < 8; ++j) mv = min(mv, top[j]);
            uint32_t best = mv;
#pragma unroll
            for (int o = 16; o; o >>= 1) best = min(best, __shfl_xor_sync(0xffffffffu, best, o));
            if (lane == 0) g_cand[r * NCAND + t] = best;
            if (mv == best) {
#pragma unroll
                for (int j = 0; j < 8; ++j) if (top[j] == best) top[j] = 0xFFFFFFFFu;
            }
        }
    };
    pops(tA, r0);
    pops(tB, r1);
}

// =============================== exact rescore (margin-pruned) + final score ===========
// One warp per query; keys ascending. Rescore prefix: lane<5, or score <= score(5th)+MARGIN.
__global__ void __launch_bounds__(128) final_kernel(const float* __restrict__ query,
                                                    const float* __restrict__ mbank,
                                                    const float* __restrict__ nscale,
                                                    float* __restrict__ out) {
    int warp = (blockIdx.x * blockDim.x + threadIdx.x) >> 5;
    int lane = threadIdx.x & 31;
    if (warp >= NQ) return;
    const int r = warp;

    uint32_t key = (lane < NCAND) ? g_cand[r * NCAND + lane] : 0xFFFFFFFFu;
    float as = __half2float(__ushort_as_half((unsigned short)(key >> 16)));
    int   ci = (int)(key & 0xFFFFu);
    const float thresh = __shfl_sync(0xffffffffu, as, 4) + MARGIN;
    bool resc = (lane < NCAND) && (lane < KNN || as <= thresh);
    int n = __popc(__ballot_sync(0xffffffffu, resc));   // prefix length (keys ascending)

    float4 qv[8];
    const float4* q4 = (const float4*)(query + (size_t)r * DIM);
#pragma unroll
    for (int c = 0; c < 8; ++c) qv[c] = q4[c * 32 + lane];
    const float q2 = g_q2[r];

    float myd = 1e30f; int myidx = 0;
    for (int t = 0; t < n; ++t) {
        int c = __shfl_sync(0xffffffffu, ci, t);
        const float4* m4 = (const float4*)(mbank + (size_t)c * DIM);
        float dot = 0.f;
#pragma unroll
        for (int j = 0; j < 8; ++j) {
            float4 mv = m4[j * 32 + lane];
            dot += qv[j].x * mv.x + qv[j].y * mv.y + qv[j].z * mv.z + qv[j].w * mv.w;
        }
#pragma unroll
        for (int o = 16; o; o >>= 1) dot += __shfl_xor_sync(0xffffffffu, dot, o);
        float d2 = q2 + g_m2[c] - 2.f * dot;
        float d  = sqrtf(fmaxf(d2, 1e-12f));
        if (lane == t) { myd = d; myidx = c; }
    }

    float dsel[KNN], ssel[KNN];
    float v = myd;
    for (int s = 0; s < KNN; ++s) {
        float bestv = v; int bestl = lane;
#pragma unroll
        for (int o = 16; o; o >>= 1) {
            float ov = __shfl_xor_sync(0xffffffffu, bestv, o);
            int   ol = __shfl_xor_sync(0xffffffffu, bestl, o);
            if (ov < bestv || (ov == bestv && ol < bestl)) { bestv = ov; bestl = ol; }
        }
        int wcand = __shfl_sync(0xffffffffu, myidx, bestl);
        dsel[s] = bestv;
        ssel[s] = nscale[wcand];
        if (lane == bestl) v = 1e30f;
    }

    float mean = 0.f, ns = 0.f, dmin = dsel[0];
#pragma unroll
    for (int s = 0; s < KNN; ++s) { mean += dsel[s]; ns += ssel[s]; dmin = fminf(dmin, dsel[s]); }
    mean *= (1.f / KNN); ns *= (1.f / KNN);
    float W = 0.f, WD = 0.f, var = 0.f;
#pragma unroll
    for (int s = 0; s < KNN; ++s) {
        float w = expf(-(dsel[s] - dmin));
        W += w; WD += w * dsel[s];
        float dd = dsel[s] - mean; var += dd * dd;
    }
    var *= (1.f / KNN);
    float wd    = WD / W;
    float cons  = sqrtf(var) / fmaxf(mean, 1e-6f);
    float normd = wd / fmaxf(ns, 1e-6f);
    if (lane == 0) out[r] = normd * (1.f + 0.5f * cons);
}

// =============================== launch ===============================
extern "C" void kernel_launch(void* const* d_in, const int* in_sizes, int n_in,
                              void* d_out, int out_size) {
    const float* query  = (const float*)d_in[0];
    const float* mbank  = (const float*)d_in[1];
    const float* nscale = (const float*)d_in[2];
    float* out = (float*)d_out;
    (void)in_sizes; (void)n_in; (void)out_size;

    int8_t *q8_p, *m8_p;
    float *q2_p, *m2_p;
    cudaGetSymbolAddress((void**)&q8_p, g_q8);
    cudaGetSymbolAddress((void**)&m8_p, g_m8);
    cudaGetSymbolAddress((void**)&q2_p, g_q2);
    cudaGetSymbolAddress((void**)&m2_p, g_m2);

    static int smem_set = 0;
    if (!smem_set) {
        cudaFuncSetAttribute(gemm_kernel, cudaFuncAttributeMaxDynamicSharedMemorySize, SMEM_DYN);
        smem_set = 1;
    }

    // 1) quantize + row sum-of-squares
    prep_kernel<<<NQ / 8, 256>>>(query, q8_p, q2_p, NQ);
    prep_kernel<<<NM / 8, 256>>>(mbank, m8_p, m2_p, NM);

    // 2) int8 similarity GEMM (occupancy 2) + fp16 score epilogue
    dim3 ggrid(NM / BN, NQ / BM);
    gemm_kernel<<<ggrid, 256, SMEM_DYN>>>();

    // 3) top-16 candidate selection, two rows per warp (ILP)
    select_kernel<<<NQ / 16, 256>>>();

    // 4) margin-pruned exact fp32 rescore + final score
    final_kernel<<<NQ / 4, 128>>>(query, mbank, nscale, out);
}

// round 17
// speedup vs baseline: 1.0333x; 1.0333x over previous
#include <cuda_runtime.h>
#include <cuda_bf16.h>
#include <cuda_fp16.h>
#include <cstdint>
#include <math.h>

#define NQ   8192
#define NM   16384
#define DIM  1024
#define KNN  5
#define NCAND 16
#define MARGIN 10.0f

#define QSCALE 24.0f
#define INV_S2 (1.0f / (24.0f * 24.0f))

// ---------------- static device scratch (no allocations allowed) ----------------
__device__ __align__(256) int8_t   g_q8[(size_t)NQ * DIM];      // 8 MB
__device__ __align__(256) int8_t   g_m8[(size_t)NM * DIM];      // 16 MB
__device__ __align__(256) float    g_q2[NQ];
__device__ __align__(256) float    g_m2[NM];
__device__ __align__(256) __half   g_Sh[(size_t)NQ * NM];       // 256 MB scores d^2-q2 (fp16, >=0)
__device__ __align__(256) uint32_t g_cand[NQ * NCAND];          // ascending keys (fp16bits<<16|col)

// =============================== helpers ===============================
__device__ __forceinline__ uint32_t smem_u32(const void* p) {
    return (uint32_t)__cvta_generic_to_shared(p);
}
__device__ __forceinline__ void cpasync16(uint32_t s, const void* g) {
    asm volatile("cp.async.cg.shared.global [%0], [%1], 16;\n" :: "r"(s), "l"(g));
}
__device__ __forceinline__ void mma_s8(int* c, const uint32_t* a, uint32_t b0, uint32_t b1) {
    asm volatile(
        "mma.sync.aligned.m16n8k32.row.col.s32.s8.s8.s32 "
        "{%0,%1,%2,%3}, {%4,%5,%6,%7}, {%8,%9}, {%0,%1,%2,%3};\n"
        : "+r"(c[0]), "+r"(c[1]), "+r"(c[2]), "+r"(c[3])
        : "r"(a[0]), "r"(a[1]), "r"(a[2]), "r"(a[3]), "r"(b0), "r"(b1));
}
__device__ __forceinline__ void ldmx4(uint32_t* r, uint32_t addr) {
    asm volatile("ldmatrix.sync.aligned.m8n8.x4.shared.b16 {%0,%1,%2,%3}, [%4];\n"
                 : "=r"(r[0]), "=r"(r[1]), "=r"(r[2]), "=r"(r[3]) : "r"(addr));
}

// =============================== prep: quantize + row sumsq ===============================
__global__ void __launch_bounds__(256) prep_kernel(const float* __restrict__ src,
                                                   int8_t* __restrict__ dst,
                                                   float* __restrict__ sq, int nrows) {
    int warp = (blockIdx.x * blockDim.x + threadIdx.x) >> 5;
    int lane = threadIdx.x & 31;
    if (warp >= nrows) return;
    const float4* s4 = (const float4*)(src + (size_t)warp * DIM);
    uint32_t* d4 = (uint32_t*)(dst + (size_t)warp * DIM);
    float acc = 0.f;
#pragma unroll
    for (int c = 0; c < DIM / 128; ++c) {
        float4 v = s4[c * 32 + lane];
        acc += v.x * v.x + v.y * v.y + v.z * v.z + v.w * v.w;
        int qa = max(-127, min(127, __float2int_rn(v.x * QSCALE)));
        int qb = max(-127, min(127, __float2int_rn(v.y * QSCALE)));
        int qc = max(-127, min(127, __float2int_rn(v.z * QSCALE)));
        int qd = max(-127, min(127, __float2int_rn(v.w * QSCALE)));
        uint32_t p = (uint32_t)(uint8_t)(int8_t)qa |
                     ((uint32_t)(uint8_t)(int8_t)qb << 8) |
                     ((uint32_t)(uint8_t)(int8_t)qc << 16) |
                     ((uint32_t)(uint8_t)(int8_t)qd << 24);
        d4[c * 32 + lane] = p;
    }
#pragma unroll
    for (int o = 16; o; o >>= 1) acc += __shfl_xor_sync(0xffffffffu, acc, o);
    if (lane == 0) sq[warp] = acc;
}

// =============================== int8 GEMM (occ-2) + fp16 score epilogue ===============================
// CTA 128x128, warp tile 64x32 (warp grid 2x4), K stage = 64 bytes, 4 stages.
// 80 KB smem + <=128 regs -> 2 CTAs/SM (proven R15 config, GEMM ~472us ~= issue floor).
#define BM 128
#define BN 128
#define BKB 64
#define STAGES 4
#define AROW 80
#define A_ST (BM * AROW)                  // 10240
#define B_ST (BN * AROW)                  // 10240
#define STAGE_BYTES (A_ST + B_ST)         // 20480
#define SMEM_DYN (STAGES * STAGE_BYTES)   // 81920
#define KTILES (DIM / BKB)                // 16

__global__ void __launch_bounds__(256, 2) gemm_kernel() {
    extern __shared__ char smem[];
    const uint32_t sb = smem_u32(smem);

    const int tid  = threadIdx.x;
    const int wid  = tid >> 5;
    const int lane = tid & 31;
    const int wm = wid & 1;            // m offset wm*64
    const int wn = wid >> 1;           // n offset wn*32
    const size_t m0 = (size_t)blockIdx.y * BM;
    const size_t n0 = (size_t)blockIdx.x * BN;

    const char* Ag = (const char*)g_q8 + m0 * DIM;
    const char* Bg = (const char*)g_m8 + n0 * DIM;

    int acc[4][4][4];
#pragma unroll
    for (int i = 0; i < 4; ++i)
#pragma unroll
        for (int j = 0; j < 4; ++j)
#pragma unroll
            for (int c = 0; c < 4; ++c) acc[i][j][c] = 0;

    auto load_stage = [&](int t, int s) {
        const uint32_t st = sb + s * STAGE_BYTES;
#pragma unroll
        for (int i = 0; i < 2; ++i) {
            int c = tid + i * 256;
            int r = c >> 2, u = c & 3;
            cpasync16(st + r * AROW + u * 16, Ag + (size_t)r * DIM + t * BKB + u * 16);
        }
#pragma unroll
        for (int i = 0; i < 2; ++i) {
            int c = tid + i * 256;
            int r = c >> 2, u = c & 3;
            cpasync16(st + A_ST + r * AROW + u * 16, Bg + (size_t)r * DIM + t * BKB + u * 16);
        }
        asm volatile("cp.async.commit_group;\n");
    };

    load_stage(0, 0);
    load_stage(1, 1);
    load_stage(2, 2);

#pragma unroll 1
    for (int kt = 0; kt < KTILES; ++kt) {
        if (kt <= 13)      asm volatile("cp.async.wait_group 2;\n" ::: "memory");
        else if (kt == 14) asm volatile("cp.async.wait_group 1;\n" ::: "memory");
        else               asm volatile("cp.async.wait_group 0;\n" ::: "memory");
        __syncthreads();

        if (kt + 3 < KTILES) load_stage(kt + 3, (kt + 3) & 3);

        const uint32_t st = sb + (kt & 3) * STAGE_BYTES;
#pragma unroll
        for (int ks = 0; ks < 2; ++ks) {
            uint32_t a[4][4], b[2][4];
            const uint32_t aAddr = st + (wm * 64 + (lane & 15)) * AROW
                                 + ks * 32 + ((lane >> 4) << 4);
#pragma unroll
            for (int i = 0; i < 4; ++i) ldmx4(a[i], aAddr + i * 16 * AROW);
            const uint32_t bAddr = st + A_ST
                                 + (wn * 32 + (lane & 7) + ((lane & 16) ? 8 : 0)) * AROW
                                 + ks * 32 + ((lane & 8) ? 16 : 0);
#pragma unroll
            for (int j = 0; j < 2; ++j) ldmx4(b[j], bAddr + j * 16 * AROW);
#pragma unroll
            for (int i = 0; i < 4; ++i)
#pragma unroll
                for (int j = 0; j < 2; ++j) {
                    mma_s8(acc[i][2 * j + 0], a[i], b[j][0], b[j][1]);
                    mma_s8(acc[i][2 * j + 1], a[i], b[j][2], b[j][3]);
                }
        }
    }

    // ---- epilogue: v = m2[col] - 2*dot*INV_S2, clamp >= 0, store fp16 ----
    const int g = lane >> 2, tig = lane & 3;
    const float* m2base = g_m2 + n0 + wn * 32;
#pragma unroll
    for (int i = 0; i < 4; ++i) {
        size_t row = m0 + wm * 64 + i * 16 + g;
        __half* o0 = g_Sh + row * NM + n0 + wn * 32;
        __half* o1 = o0 + (size_t)8 * NM;
#pragma unroll
        for (int j = 0; j < 4; ++j) {
            int col = j * 8 + 2 * tig;
            float2 m2v = *(const float2*)(m2base + col);
            float v00 = fmaxf(m2v.x - 2.f * INV_S2 * __int2float_rn(acc[i][j][0]), 0.f);
            float v01 = fmaxf(m2v.y - 2.f * INV_S2 * __int2float_rn(acc[i][j][1]), 0.f);
            float v10 = fmaxf(m2v.x - 2.f * INV_S2 * __int2float_rn(acc[i][j][2]), 0.f);
            float v11 = fmaxf(m2v.y - 2.f * INV_S2 * __int2float_rn(acc[i][j][3]), 0.f);
            *(__half2*)(o0 + col) = __floats2half2_rn(v00, v01);
            *(__half2*)(o1 + col) = __floats2half2_rn(v10, v11);
        }
    }
}

// =============================== candidate selection (R15-proven, full keys) ============
__global__ void __launch_bounds__(256) select_kernel() {
    int warp = (blockIdx.x * blockDim.x + threadIdx.x) >> 5;
    int lane = threadIdx.x & 31;
    if (warp >= NQ) return;
    const __half* Srow = g_Sh + (size_t)warp * NM;

    uint32_t top[8];
#pragma unroll
    for (int j = 0; j < 8; ++j) top[j] = 0xFFFFFFFFu;

    for (int it = 0; it < NM / 256; ++it) {
        int c0 = it * 256 + lane * 8;
        uint4 raw = *(const uint4*)(Srow + c0);
        uint32_t w[4] = { raw.x, raw.y, raw.z, raw.w };
#pragma unroll
        for (int q = 0; q < 4; ++q) {
            uint32_t klo = (w[q] << 16) | (uint32_t)(c0 + 2 * q);
            uint32_t khi = (w[q] & 0xFFFF0000u) | (uint32_t)(c0 + 2 * q + 1);
#pragma unroll
            for (int s = 0; s < 2; ++s) {
                uint32_t key = s ? khi : klo;
                if (key < top[7]) {
                    top[7] = key;
#pragma unroll
                    for (int j = 7; j > 0; --j) {
                        if (top[j] < top[j - 1]) { uint32_t t2 = top[j]; top[j] = top[j - 1]; top[j - 1] = t2; }
                    }
                }
            }
        }
    }

    // 16 warp-min pops -> full keys, ascending
    for (int t = 0; t < NCAND; ++t) {
        uint32_t mv = top[0];
#pragma unroll
        for (int j = 1; j < 8; ++j) mv = min(mv, top[j]);
        uint32_t best = mv;
#pragma unroll
        for (int o = 16; o; o >>= 1) best = min(best, __shfl_xor_sync(0xffffffffu, best, o));
        if (lane == 0) g_cand[warp * NCAND + t] = best;
        if (mv == best) {
#pragma unroll
            for (int j = 0; j < 8; ++j) if (top[j] == best) top[j] = 0xFFFFFFFFu;
        }
    }
}

// =============================== exact rescore (margin-pruned) + final score ===========
// One warp per query; keys ascending. Rescore prefix: lane<5, or score <= score(5th)+MARGIN.
__global__ void __launch_bounds__(128) final_kernel(const float* __restrict__ query,
                                                    const float* __restrict__ mbank,
                                                    const float* __restrict__ nscale,
                                                    float* __restrict__ out) {
    int warp = (blockIdx.x * blockDim.x + threadIdx.x) >> 5;
    int lane = threadIdx.x & 31;
    if (warp >= NQ) return;
    const int r = warp;

    uint32_t key = (lane < NCAND) ? g_cand[r * NCAND + lane] : 0xFFFFFFFFu;
    float as = __half2float(__ushort_as_half((unsigned short)(key >> 16)));
    int   ci = (int)(key & 0xFFFFu);
    const float thresh = __shfl_sync(0xffffffffu, as, 4) + MARGIN;
    bool resc = (lane < NCAND) && (lane < KNN || as <= thresh);
    int n = __popc(__ballot_sync(0xffffffffu, resc));   // prefix length (keys ascending)

    float4 qv[8];
    const float4* q4 = (const float4*)(query + (size_t)r * DIM);
#pragma unroll
    for (int c = 0; c < 8; ++c) qv[c] = q4[c * 32 + lane];
    const float q2 = g_q2[r];

    float myd = 1e30f; int myidx = 0;
    for (int t = 0; t < n; ++t) {
        int c = __shfl_sync(0xffffffffu, ci, t);
        const float4* m4 = (const float4*)(mbank + (size_t)c * DIM);
        float dot = 0.f;
#pragma unroll
        for (int j = 0; j < 8; ++j) {
            float4 mv = m4[j * 32 + lane];
            dot += qv[j].x * mv.x + qv[j].y * mv.y + qv[j].z * mv.z + qv[j].w * mv.w;
        }
#pragma unroll
        for (int o = 16; o; o >>= 1) dot += __shfl_xor_sync(0xffffffffu, dot, o);
        float d2 = q2 + g_m2[c] - 2.f * dot;
        float d  = sqrtf(fmaxf(d2, 1e-12f));
        if (lane == t) { myd = d; myidx = c; }
    }

    float dsel[KNN], ssel[KNN];
    float v = myd;
    for (int s = 0; s < KNN; ++s) {
        float bestv = v; int bestl = lane;
#pragma unroll
        for (int o = 16; o; o >>= 1) {
            float ov = __shfl_xor_sync(0xffffffffu, bestv, o);
            int   ol = __shfl_xor_sync(0xffffffffu, bestl, o);
            if (ov < bestv || (ov == bestv && ol < bestl)) { bestv = ov; bestl = ol; }
        }
        int wcand = __shfl_sync(0xffffffffu, myidx, bestl);
        dsel[s] = bestv;
        ssel[s] = nscale[wcand];
        if (lane == bestl) v = 1e30f;
    }

    float mean = 0.f, ns = 0.f, dmin = dsel[0];
#pragma unroll
    for (int s = 0; s < KNN; ++s) { mean += dsel[s]; ns += ssel[s]; dmin = fminf(dmin, dsel[s]); }
    mean *= (1.f / KNN); ns *= (1.f / KNN);
    float W = 0.f, WD = 0.f, var = 0.f;
#pragma unroll
    for (int s = 0; s < KNN; ++s) {
        float w = expf(-(dsel[s] - dmin));
        W += w; WD += w * dsel[s];
        float dd = dsel[s] - mean; var += dd * dd;
    }
    var *= (1.f / KNN);
    float wd    = WD / W;
    float cons  = sqrtf(var) / fmaxf(mean, 1e-6f);
    float normd = wd / fmaxf(ns, 1e-6f);
    if (lane == 0) out[r] = normd * (1.f + 0.5f * cons);
}

// =============================== launch ===============================
extern "C" void kernel_launch(void* const* d_in, const int* in_sizes, int n_in,
                              void* d_out, int out_size) {
    const float* query  = (const float*)d_in[0];
    const float* mbank  = (const float*)d_in[1];
    const float* nscale = (const float*)d_in[2];
    float* out = (float*)d_out;
    (void)in_sizes; (void)n_in; (void)out_size;

    int8_t *q8_p, *m8_p;
    float *q2_p, *m2_p;
    cudaGetSymbolAddress((void**)&q8_p, g_q8);
    cudaGetSymbolAddress((void**)&m8_p, g_m8);
    cudaGetSymbolAddress((void**)&q2_p, g_q2);
    cudaGetSymbolAddress((void**)&m2_p, g_m2);

    static int smem_set = 0;
    if (!smem_set) {
        cudaFuncSetAttribute(gemm_kernel, cudaFuncAttributeMaxDynamicSharedMemorySize, SMEM_DYN);
        smem_set = 1;
    }

    // 1) quantize + row sum-of-squares
    prep_kernel<<<NQ / 8, 256>>>(query, q8_p, q2_p, NQ);
    prep_kernel<<<NM / 8, 256>>>(mbank, m8_p, m2_p, NM);

    // 2) int8 similarity GEMM (occupancy 2) + fp16 score epilogue
    dim3 ggrid(NM / BN, NQ / BM);
    gemm_kernel<<<ggrid, 256, SMEM_DYN>>>();

    // 3) top-16 candidate selection per query (one row per warp)
    select_kernel<<<NQ / 8, 256>>>();

    // 4) margin-pruned exact fp32 rescore + final score
    final_kernel<<<NQ / 4, 128>>>(query, mbank, nscale, out);
}